// round 3
// baseline (speedup 1.0000x reference)
#include <cuda_runtime.h>
#include <stdint.h>

#define FULLM 0xFFFFFFFFu
#define NW 8   // warps (rows) per block

__constant__ uint32_t cK[64] = {
    0xd76aa478u,0xe8c7b756u,0x242070dbu,0xc1bdceeeu,
    0xf57c0fafu,0x4787c62au,0xa8304613u,0xfd469501u,
    0x698098d8u,0x8b44f7afu,0xffff5bb1u,0x895cd7beu,
    0x6b901122u,0xfd987193u,0xa679438eu,0x49b40821u,
    0xf61e2562u,0xc040b340u,0x265e5a51u,0xe9b6c7aau,
    0xd62f105du,0x02441453u,0xd8a1e681u,0xe7d3fbc8u,
    0x21e1cde6u,0xc33707d6u,0xf4d50d87u,0x455a14edu,
    0xa9e3e905u,0xfcefa3f8u,0x676f02d9u,0x8d2a4c8au,
    0xfffa3942u,0x8771f681u,0x6d9d6122u,0xfde5380cu,
    0xa4beea44u,0x4bdecfa9u,0xf6bb4b60u,0xbebfbc70u,
    0x289b7ec6u,0xeaa127fau,0xd4ef3085u,0x04881d05u,
    0xd9d4d039u,0xe6db99e5u,0x1fa27cf8u,0xc4ac5665u,
    0xf4292244u,0x432aff97u,0xab9423a7u,0xfc93a039u,
    0x655b59c3u,0x8f0ccc92u,0xffeff47du,0x85845dd1u,
    0x6fa87e4fu,0xfe2ce6e0u,0xa3014314u,0x4e0811a1u,
    0xf7537e82u,0xbd3af235u,0x2ad7d2bbu,0xeb86d391u };

__constant__ int cS[64] = {
    7,12,17,22, 7,12,17,22, 7,12,17,22, 7,12,17,22,
    5, 9,14,20, 5, 9,14,20, 5, 9,14,20, 5, 9,14,20,
    4,11,16,23, 4,11,16,23, 4,11,16,23, 4,11,16,23,
    6,10,15,21, 6,10,15,21, 6,10,15,21, 6,10,15,21 };

__constant__ uint32_t cPW[16] = { 0x80u,0,0,0, 0,0,0,0, 0,0,0,0, 0,0, 0x200u,0 };

// ---- f32 soft ops, exact IEEE-RN with the Python association ---------------
__device__ __forceinline__ float fxor(float a, float b) {
    return __fsub_rn(__fadd_rn(a, b), __fmul_rn(__fmul_rn(2.0f, a), b));
}
__device__ __forceinline__ float fand(float a, float b) { return __fmul_rn(a, b); }
__device__ __forceinline__ float forr(float a, float b) {
    return __fsub_rn(__fadd_rn(a, b), __fmul_rn(a, b));
}
__device__ __forceinline__ float fnot(float a) { return __fsub_rn(1.0f, a); }

// ---- RN to 53-bit significand (ties-to-even) of a nonneg u64 ---------------
__device__ __forceinline__ uint64_t rn53(uint64_t x) {
    if (x < (1ull << 53)) return x;
    int n = 64 - __clzll(x);
    int s = n - 53;
    uint64_t keep = x >> s;
    uint64_t half = 1ull << (s - 1);
    uint64_t rem  = x & ((half << 1) - 1ull);
    keep += (rem > half) || (rem == half && (keep & 1ull));
    return keep << s;
}

// ---- f64 term = (double)f * 2^lane, built by integer bit surgery -----------
__device__ __forceinline__ double term(float f, int lane) {
    uint32_t b = __float_as_uint(f);
    if ((b & 0x7FFFFFFFu) == 0u) return 0.0;
    uint64_t e = (uint64_t)((b >> 23) & 0xFFu) + (uint64_t)(1023 - 127 + lane);
    uint64_t d = ((uint64_t)(b & 0x80000000u) << 32) | (e << 52) |
                 ((uint64_t)(b & 0x7FFFFFu) << 29);
    return __longlong_as_double((long long)d);
}

// ---- strict sequential (lane 0 -> 31) f64 sum: XLA:CPU reduce order --------
__device__ __forceinline__ double seq_reduce(double t) {
    double s = __shfl_sync(FULLM, t, 0);
#pragma unroll
    for (int k = 1; k < 32; k++)
        s = __dadd_rn(s, __shfl_sync(FULLM, t, k));
    return s;
}

// ---- value of a T-valued bit vector ({0,1,1-2^-24}) in 2^-24 units ---------
// Sequential f64 sum is EXACT through lane 28; rn53 emulates lanes 29..31.
__device__ __forceinline__ uint64_t tval_ballots(uint32_t bh, uint32_t bp) {
    uint64_t E = (((uint64_t)(bh & 0x1FFFFFFFu)) << 24) - (uint64_t)(bp & 0x1FFFFFFFu);
#pragma unroll
    for (int i = 29; i < 32; i++) {
        uint64_t t = (((uint64_t)((bh >> i) & 1u)) << (24 + i)) -
                     (((uint64_t)((bp >> i) & 1u)) << i);
        E = rn53(E + t);
    }
    return E;
}
__device__ __forceinline__ uint64_t tval_from(float v) {
    uint32_t bh = __ballot_sync(FULLM, v > 0.5f);
    uint32_t bp = __ballot_sync(FULLM, (v > 0.5f) && (v < 1.0f));
    return tval_ballots(bh, bp);
}

// ---- hard add: u64 x u64 (both RN53-clean, 2^-24 units) --------------------
__device__ __forceinline__ uint32_t hard_uu(uint64_t a, uint64_t b) {
    uint64_t s = rn53(a + b);                 // f64 RN of the add
    if (s >= (1ull << 56)) s -= (1ull << 56); // fmod(., 2^32), exact
    return (uint32_t)(s >> 24);               // floor
}
__device__ __forceinline__ double u2d(uint64_t v) {
    return __dmul_rn((double)v, 5.9604644775390625e-8); // * 2^-24, exact
}
// ---- hard add: f64 x f64 ----------------------------------------------------
__device__ __forceinline__ uint32_t hard_dd(double x, double y) {
    double s = __dadd_rn(x, y);
    if (s >= 4294967296.0) s = __dsub_rn(s, 4294967296.0);  // exact fmod
    return (uint32_t)(unsigned long long)s;                 // floor
}
// ---- soft_add32 output bit: fl(fl(h+px)-px) --------------------------------
__device__ __forceinline__ float out_bit(float ab, float bb, uint32_t u, int lane) {
    float h = (float)((u >> lane) & 1u);
    float px = __fmul_rn(fxor(ab, bb), 0.5f);
    return __fsub_rn(__fadd_rn(h, px), px);
}

template <int PAD>
__device__ void compress(float& FA, float& FB, float& FC, float& FD,
                         uint64_t& VA, uint64_t& VB, uint64_t& VC, uint64_t& VD,
                         const float* __restrict__ wb, const double* __restrict__ wv,
                         int lane)
{
    float a = FA, b = FB, c = FC, d = FD;
    uint64_t va = VA, vb = VB, vc = VC, vd = VD;

    for (int i = 0; i < 64; i++) {
        float f; int g;
        int ph = i >> 4;
        if (ph == 0)      { f = forr(fand(b, c), fand(fnot(b), d)); g = i; }
        else if (ph == 1) { f = forr(fand(d, b), fand(fnot(d), c)); g = (5 * i + 1) & 15; }
        else if (ph == 2) { f = fxor(fxor(b, c), d);                g = (3 * i + 5) & 15; }
        else              { f = fxor(c, forr(b, fnot(d)));          g = (7 * i) & 15; }

        // soft_add32(f, a): f has fine-grid bits -> faithful f64 chain
        double vf = seq_reduce(term(f, lane));
        uint32_t u1 = hard_dd(vf, u2d(va));
        float f1 = out_bit(f, a, u1, lane);
        uint64_t v1 = tval_from(f1);

        // soft_add32(f1, K[i]): both T/integer -> u64 path
        uint32_t Ki = cK[i];
        uint32_t u2 = hard_uu(v1, ((uint64_t)Ki) << 24);
        float kb = (float)((Ki >> lane) & 1u);
        float f2 = out_bit(f1, kb, u2, lane);
        uint64_t v2 = tval_from(f2);

        // soft_add32(f2, words[g])
        float wbit; uint32_t u3;
        if (PAD) {
            uint32_t pw = cPW[g];
            wbit = (float)((pw >> lane) & 1u);
            u3 = hard_uu(v2, ((uint64_t)pw) << 24);
        } else {
            wbit = wb[g * 32 + lane];
            u3 = hard_dd(u2d(v2), wv[g]);
        }
        float f3 = out_bit(f2, wbit, u3, lane);

        // rotate f3 left by S[i]; value from rotated ballots (f3 is T-valued)
        uint32_t bh3 = __ballot_sync(FULLM, f3 > 0.5f);
        uint32_t bp3 = __ballot_sync(FULLM, (f3 > 0.5f) && (f3 < 1.0f));
        int sh = cS[i];
        uint32_t bhr = __funnelshift_l(bh3, bh3, sh);
        uint32_t bpr = __funnelshift_l(bp3, bp3, sh);
        uint64_t vrot = tval_ballots(bhr, bpr);
        float rot = __shfl_sync(FULLM, f3, (lane - sh) & 31);

        // b = soft_add32(b, rot)
        uint32_t u4 = hard_uu(vb, vrot);
        float nb = out_bit(b, rot, u4, lane);
        uint64_t vnb = tval_from(nb);

        a = d;  va = vd;
        d = c;  vd = vc;
        c = b;  vc = vb;
        b = nb; vb = vnb;
    }

    // H update: X = soft_add32(X_init, X_final)
    uint32_t uA = hard_uu(VA, va); float nA = out_bit(FA, a, uA, lane);
    uint32_t uB = hard_uu(VB, vb); float nB = out_bit(FB, b, uB, lane);
    uint32_t uC = hard_uu(VC, vc); float nC = out_bit(FC, c, uC, lane);
    uint32_t uD = hard_uu(VD, vd); float nD = out_bit(FD, d, uD, lane);
    FA = nA; VA = tval_from(nA);
    FB = nB; VB = tval_from(nB);
    FC = nC; VC = tval_from(nC);
    FD = nD; VD = tval_from(nD);
}

__global__ void __launch_bounds__(NW * 32)
softmd5_kernel(const float* __restrict__ in, float* __restrict__ out, int B)
{
    int lane = threadIdx.x & 31;
    int wib  = threadIdx.x >> 5;
    int row  = blockIdx.x * NW + wib;
    if (row >= B) return;   // B divisible by NW -> whole warps, ballots safe

    __shared__ float  swb[NW][16][32];
    __shared__ double swv[NW][16];

    const float* rp = in + (size_t)row * 512;
#pragma unroll
    for (int g = 0; g < 16; g++) {
        float v = rp[g * 32 + lane];
        swb[wib][g][lane] = v;
        double s = seq_reduce(term(v, lane));   // word value, seq f64 order
        if (lane == 0) swv[wib][g] = s;
    }
    __syncwarp();

    float FA = (float)((0x67452301u >> lane) & 1u);
    float FB = (float)((0xefcdab89u >> lane) & 1u);
    float FC = (float)((0x98badcfeu >> lane) & 1u);
    float FD = (float)((0x10325476u >> lane) & 1u);
    uint64_t VA = ((uint64_t)0x67452301u) << 24;
    uint64_t VB = ((uint64_t)0xefcdab89u) << 24;
    uint64_t VC = ((uint64_t)0x98badcfeu) << 24;
    uint64_t VD = ((uint64_t)0x10325476u) << 24;

    compress<0>(FA, FB, FC, FD, VA, VB, VC, VD,
                &swb[wib][0][0], swv[wib], lane);
    compress<1>(FA, FB, FC, FD, VA, VB, VC, VD,
                &swb[wib][0][0], swv[wib], lane);

    float* op = out + (size_t)row * 128;
    op[lane]      = FA;
    op[32 + lane] = FB;
    op[64 + lane] = FC;
    op[96 + lane] = FD;
}

extern "C" void kernel_launch(void* const* d_in, const int* in_sizes, int n_in,
                              void* d_out, int out_size)
{
    const float* in = (const float*)d_in[0];
    float* out = (float*)d_out;
    int B = in_sizes[0] / 512;             // 131072 rows
    int blocks = (B + NW - 1) / NW;
    softmd5_kernel<<<blocks, NW * 32>>>(in, out, B);
}

// round 4
// speedup vs baseline: 1.0030x; 1.0030x over previous
#include <cuda_runtime.h>
#include <stdint.h>

#define FULLM 0xFFFFFFFFu
#define NW 8   // warps (rows) per block

__constant__ uint32_t cK[64] = {
    0xd76aa478u,0xe8c7b756u,0x242070dbu,0xc1bdceeeu,
    0xf57c0fafu,0x4787c62au,0xa8304613u,0xfd469501u,
    0x698098d8u,0x8b44f7afu,0xffff5bb1u,0x895cd7beu,
    0x6b901122u,0xfd987193u,0xa679438eu,0x49b40821u,
    0xf61e2562u,0xc040b340u,0x265e5a51u,0xe9b6c7aau,
    0xd62f105du,0x02441453u,0xd8a1e681u,0xe7d3fbc8u,
    0x21e1cde6u,0xc33707d6u,0xf4d50d87u,0x455a14edu,
    0xa9e3e905u,0xfcefa3f8u,0x676f02d9u,0x8d2a4c8au,
    0xfffa3942u,0x8771f681u,0x6d9d6122u,0xfde5380cu,
    0xa4beea44u,0x4bdecfa9u,0xf6bb4b60u,0xbebfbc70u,
    0x289b7ec6u,0xeaa127fau,0xd4ef3085u,0x04881d05u,
    0xd9d4d039u,0xe6db99e5u,0x1fa27cf8u,0xc4ac5665u,
    0xf4292244u,0x432aff97u,0xab9423a7u,0xfc93a039u,
    0x655b59c3u,0x8f0ccc92u,0xffeff47du,0x85845dd1u,
    0x6fa87e4fu,0xfe2ce6e0u,0xa3014314u,0x4e0811a1u,
    0xf7537e82u,0xbd3af235u,0x2ad7d2bbu,0xeb86d391u };

__constant__ int cS[64] = {
    7,12,17,22, 7,12,17,22, 7,12,17,22, 7,12,17,22,
    5, 9,14,20, 5, 9,14,20, 5, 9,14,20, 5, 9,14,20,
    4,11,16,23, 4,11,16,23, 4,11,16,23, 4,11,16,23,
    6,10,15,21, 6,10,15,21, 6,10,15,21, 6,10,15,21 };

__constant__ uint32_t cPW[16] = { 0x80u,0,0,0, 0,0,0,0, 0,0,0,0, 0,0, 0x200u,0 };

// ---- f32 soft ops, exact IEEE-RN with the Python association ---------------
__device__ __forceinline__ float fxor(float a, float b) {
    return __fsub_rn(__fadd_rn(a, b), __fmul_rn(__fmul_rn(2.0f, a), b));
}
__device__ __forceinline__ float fand(float a, float b) { return __fmul_rn(a, b); }
__device__ __forceinline__ float forr(float a, float b) {
    return __fsub_rn(__fadd_rn(a, b), __fmul_rn(a, b));
}
__device__ __forceinline__ float fnot(float a) { return __fsub_rn(1.0f, a); }

// ---- RN to 53-bit significand (ties-to-even) of a nonneg u64 ---------------
__device__ __forceinline__ uint64_t rn53(uint64_t x) {
    if (x < (1ull << 53)) return x;
    int n = 64 - __clzll(x);
    int s = n - 53;
    uint64_t keep = x >> s;
    uint64_t half = 1ull << (s - 1);
    uint64_t rem  = x & ((half << 1) - 1ull);
    keep += (rem > half) || (rem == half && (keep & 1ull));
    return keep << s;
}

// ---- f64 term = (double)f * 2^lane, built by integer bit surgery -----------
__device__ __forceinline__ double term(float f, int lane) {
    uint32_t b = __float_as_uint(f);
    if ((b & 0x7FFFFFFFu) == 0u) return 0.0;
    uint64_t e = (uint64_t)((b >> 23) & 0xFFu) + (uint64_t)(1023 - 127 + lane);
    uint64_t d = ((uint64_t)(b & 0x80000000u) << 32) | (e << 52) |
                 ((uint64_t)(b & 0x7FFFFFu) << 29);
    return __longlong_as_double((long long)d);
}

// ---- strict sequential (lane 0 -> 31) f64 sum: XLA:CPU reduce order --------
__device__ __forceinline__ double seq_reduce(double t) {
    double s = __shfl_sync(FULLM, t, 0);
#pragma unroll
    for (int k = 1; k < 32; k++)
        s = __dadd_rn(s, __shfl_sync(FULLM, t, k));
    return s;
}

// ---- value of a T-valued bit vector ({0,1,1-2^-24}) in 2^-24 units ---------
// Sequential f64 sum is EXACT through lane 28; rn53 emulates lanes 29..31.
__device__ __forceinline__ uint64_t tval_ballots(uint32_t bh, uint32_t bp) {
    uint64_t E = (((uint64_t)(bh & 0x1FFFFFFFu)) << 24) - (uint64_t)(bp & 0x1FFFFFFFu);
#pragma unroll
    for (int i = 29; i < 32; i++) {
        uint64_t t = (((uint64_t)((bh >> i) & 1u)) << (24 + i)) -
                     (((uint64_t)((bp >> i) & 1u)) << i);
        E = rn53(E + t);
    }
    return E;
}
__device__ __forceinline__ uint64_t tval_from(float v) {
    uint32_t bh = __ballot_sync(FULLM, v > 0.5f);
    uint32_t bp = __ballot_sync(FULLM, (v > 0.5f) && (v < 1.0f));
    return tval_ballots(bh, bp);
}

// ---- hard add: u64 x u64 (both RN53-clean, 2^-24 units) --------------------
__device__ __forceinline__ uint32_t hard_uu(uint64_t a, uint64_t b) {
    uint64_t s = rn53(a + b);                 // f64 RN of the add
    if (s >= (1ull << 56)) s -= (1ull << 56); // fmod(., 2^32), exact
    return (uint32_t)(s >> 24);               // floor
}
__device__ __forceinline__ double u2d(uint64_t v) {
    return __dmul_rn((double)v, 5.9604644775390625e-8); // * 2^-24, exact
}
// ---- hard add: f64 x f64 ----------------------------------------------------
__device__ __forceinline__ uint32_t hard_dd(double x, double y) {
    double s = __dadd_rn(x, y);
    if (s >= 4294967296.0) s = __dsub_rn(s, 4294967296.0);  // exact fmod
    return (uint32_t)(unsigned long long)s;                 // floor
}
// ---- soft_add32 output bit: fl(fl(h+px)-px) --------------------------------
__device__ __forceinline__ float out_bit(float ab, float bb, uint32_t u, int lane) {
    float h = (float)((u >> lane) & 1u);
    float px = __fmul_rn(fxor(ab, bb), 0.5f);
    return __fsub_rn(__fadd_rn(h, px), px);
}

template <int PAD>
__device__ void compress(float& FA, float& FB, float& FC, float& FD,
                         uint64_t& VA, uint64_t& VB, uint64_t& VC, uint64_t& VD,
                         const float* __restrict__ wb, const double* __restrict__ wv,
                         int lane)
{
    float a = FA, b = FB, c = FC, d = FD;
    uint64_t va = VA, vb = VB, vc = VC, vd = VD;

    for (int i = 0; i < 64; i++) {
        float f; int g;
        int ph = i >> 4;
        if (ph == 0)      { f = forr(fand(b, c), fand(fnot(b), d)); g = i; }
        else if (ph == 1) { f = forr(fand(d, b), fand(fnot(d), c)); g = (5 * i + 1) & 15; }
        else if (ph == 2) { f = fxor(fxor(b, c), d);                g = (3 * i + 5) & 15; }
        else              { f = fxor(c, forr(b, fnot(d)));          g = (7 * i) & 15; }

        // soft_add32(f, a): f has fine-grid bits -> faithful f64 chain
        double vf = seq_reduce(term(f, lane));
        uint32_t u1 = hard_dd(vf, u2d(va));
        float f1 = out_bit(f, a, u1, lane);
        uint64_t v1 = tval_from(f1);

        // soft_add32(f1, K[i]): both T/integer -> u64 path
        uint32_t Ki = cK[i];
        uint32_t u2 = hard_uu(v1, ((uint64_t)Ki) << 24);
        float kb = (float)((Ki >> lane) & 1u);
        float f2 = out_bit(f1, kb, u2, lane);
        uint64_t v2 = tval_from(f2);

        // soft_add32(f2, words[g])
        float wbit; uint32_t u3;
        if (PAD) {
            uint32_t pw = cPW[g];
            wbit = (float)((pw >> lane) & 1u);
            u3 = hard_uu(v2, ((uint64_t)pw) << 24);
        } else {
            wbit = wb[g * 32 + lane];
            u3 = hard_dd(u2d(v2), wv[g]);
        }
        float f3 = out_bit(f2, wbit, u3, lane);

        // rotate f3 left by S[i]; value from rotated ballots (f3 is T-valued)
        uint32_t bh3 = __ballot_sync(FULLM, f3 > 0.5f);
        uint32_t bp3 = __ballot_sync(FULLM, (f3 > 0.5f) && (f3 < 1.0f));
        int sh = cS[i];
        uint32_t bhr = __funnelshift_l(bh3, bh3, sh);
        uint32_t bpr = __funnelshift_l(bp3, bp3, sh);
        uint64_t vrot = tval_ballots(bhr, bpr);
        float rot = __shfl_sync(FULLM, f3, (lane - sh) & 31);

        // b = soft_add32(b, rot)
        uint32_t u4 = hard_uu(vb, vrot);
        float nb = out_bit(b, rot, u4, lane);
        uint64_t vnb = tval_from(nb);

        a = d;  va = vd;
        d = c;  vd = vc;
        c = b;  vc = vb;
        b = nb; vb = vnb;
    }

    // H update: X = soft_add32(X_init, X_final)
    uint32_t uA = hard_uu(VA, va); float nA = out_bit(FA, a, uA, lane);
    uint32_t uB = hard_uu(VB, vb); float nB = out_bit(FB, b, uB, lane);
    uint32_t uC = hard_uu(VC, vc); float nC = out_bit(FC, c, uC, lane);
    uint32_t uD = hard_uu(VD, vd); float nD = out_bit(FD, d, uD, lane);
    FA = nA; VA = tval_from(nA);
    FB = nB; VB = tval_from(nB);
    FC = nC; VC = tval_from(nC);
    FD = nD; VD = tval_from(nD);
}

__global__ void __launch_bounds__(NW * 32)
softmd5_kernel(const float* __restrict__ in, float* __restrict__ out, int B)
{
    int lane = threadIdx.x & 31;
    int wib  = threadIdx.x >> 5;
    int row  = blockIdx.x * NW + wib;
    if (row >= B) return;   // B divisible by NW -> whole warps, ballots safe

    __shared__ float  swb[NW][16][32];
    __shared__ double swv[NW][16];

    const float* rp = in + (size_t)row * 512;
#pragma unroll
    for (int g = 0; g < 16; g++) {
        float v = rp[g * 32 + lane];
        swb[wib][g][lane] = v;
        double s = seq_reduce(term(v, lane));   // word value, seq f64 order
        if (lane == 0) swv[wib][g] = s;
    }
    __syncwarp();

    float FA = (float)((0x67452301u >> lane) & 1u);
    float FB = (float)((0xefcdab89u >> lane) & 1u);
    float FC = (float)((0x98badcfeu >> lane) & 1u);
    float FD = (float)((0x10325476u >> lane) & 1u);
    uint64_t VA = ((uint64_t)0x67452301u) << 24;
    uint64_t VB = ((uint64_t)0xefcdab89u) << 24;
    uint64_t VC = ((uint64_t)0x98badcfeu) << 24;
    uint64_t VD = ((uint64_t)0x10325476u) << 24;

    compress<0>(FA, FB, FC, FD, VA, VB, VC, VD,
                &swb[wib][0][0], swv[wib], lane);
    compress<1>(FA, FB, FC, FD, VA, VB, VC, VD,
                &swb[wib][0][0], swv[wib], lane);

    float* op = out + (size_t)row * 128;
    op[lane]      = FA;
    op[32 + lane] = FB;
    op[64 + lane] = FC;
    op[96 + lane] = FD;
}

extern "C" void kernel_launch(void* const* d_in, const int* in_sizes, int n_in,
                              void* d_out, int out_size)
{
    const float* in = (const float*)d_in[0];
    float* out = (float*)d_out;
    int B = in_sizes[0] / 512;             // 131072 rows
    int blocks = (B + NW - 1) / NW;
    softmd5_kernel<<<blocks, NW * 32>>>(in, out, B);
}

// round 5
// speedup vs baseline: 16.9229x; 16.8728x over previous
#include <cuda_runtime.h>
#include <stdint.h>

#define TPB 128

__constant__ uint32_t cK[64] = {
    0xd76aa478u,0xe8c7b756u,0x242070dbu,0xc1bdceeeu,
    0xf57c0fafu,0x4787c62au,0xa8304613u,0xfd469501u,
    0x698098d8u,0x8b44f7afu,0xffff5bb1u,0x895cd7beu,
    0x6b901122u,0xfd987193u,0xa679438eu,0x49b40821u,
    0xf61e2562u,0xc040b340u,0x265e5a51u,0xe9b6c7aau,
    0xd62f105du,0x02441453u,0xd8a1e681u,0xe7d3fbc8u,
    0x21e1cde6u,0xc33707d6u,0xf4d50d87u,0x455a14edu,
    0xa9e3e905u,0xfcefa3f8u,0x676f02d9u,0x8d2a4c8au,
    0xfffa3942u,0x8771f681u,0x6d9d6122u,0xfde5380cu,
    0xa4beea44u,0x4bdecfa9u,0xf6bb4b60u,0xbebfbc70u,
    0x289b7ec6u,0xeaa127fau,0xd4ef3085u,0x04881d05u,
    0xd9d4d039u,0xe6db99e5u,0x1fa27cf8u,0xc4ac5665u,
    0xf4292244u,0x432aff97u,0xab9423a7u,0xfc93a039u,
    0x655b59c3u,0x8f0ccc92u,0xffeff47du,0x85845dd1u,
    0x6fa87e4fu,0xfe2ce6e0u,0xa3014314u,0x4e0811a1u,
    0xf7537e82u,0xbd3af235u,0x2ad7d2bbu,0xeb86d391u };

// ---- f32 soft ops, exact IEEE-RN, reference association --------------------
__device__ __forceinline__ float fxor(float a, float b) {
    return __fsub_rn(__fadd_rn(a, b), __fmul_rn(__fmul_rn(2.0f, a), b));
}
__device__ __forceinline__ float fand(float a, float b) { return __fmul_rn(a, b); }
__device__ __forceinline__ float forr(float a, float b) {
    return __fsub_rn(__fadd_rn(a, b), __fmul_rn(a, b));
}
__device__ __forceinline__ float fnot(float a) { return __fsub_rn(1.0f, a); }

// state code: bit0 = hard bit, bit1 = deficit (value 1-2^-24)
__device__ __forceinline__ float decst(int st) {
    if (!(st & 1)) return 0.0f;
    return (st & 2) ? __uint_as_float(0x3F7FFFFFu) : 1.0f;
}
__device__ __forceinline__ float fphase(int ph, float b, float c, float d) {
    if (ph == 0) return forr(fand(b, c), fand(fnot(b), d));
    if (ph == 1) return forr(fand(d, b), fand(fnot(d), c));
    if (ph == 2) return fxor(fxor(b, c), d);
    return fxor(c, forr(b, fnot(d)));
}
// deficit predicate: soft_add32 result bit is (1-2^-24) iff hard=1 AND this
__device__ __forceinline__ uint32_t pbit(float x, float y) {
    float px = __fmul_rn(fxor(x, y), 0.5f);
    float r  = __fsub_rn(__fadd_rn(1.0f, px), px);
    return (__float_as_uint(r) != 0x3F800000u) ? 1u : 0u;
}

// ---- RN to 53-bit significand (ties-to-even) of a nonneg u64 ---------------
__device__ __forceinline__ uint64_t rn53(uint64_t x) {
    if (x < (1ull << 53)) return x;
    int n = 64 - __clzll(x);
    int s = n - 53;
    uint64_t keep = x >> s;
    uint64_t half = 1ull << (s - 1);
    uint64_t rem  = x & ((half << 1) - 1ull);
    keep += (rem > half) || (rem == half && (keep & 1ull));
    return keep << s;
}
// sequential f64 value of a T-valued word, 2^-24 units (R3-validated)
__device__ __forceinline__ uint64_t tvalm(uint32_t H, uint32_t P) {
    uint64_t E = (((uint64_t)(H & 0x1FFFFFFFu)) << 24) - (uint64_t)(P & 0x1FFFFFFFu);
#pragma unroll
    for (int i = 29; i < 32; i++) {
        uint64_t t = (((uint64_t)((H >> i) & 1u)) << (24 + i)) -
                     (((uint64_t)((P >> i) & 1u)) << i);
        E = rn53(E + t);
    }
    return E;
}
// hard bits of f64 add of two T-word values (both rn53-clean, 2^-24 units)
__device__ __forceinline__ uint32_t hard_uu(uint64_t a, uint64_t b) {
    uint64_t t = rn53(a + b);
    return (uint32_t)(t >> 24);   // floor + mod 2^32 via truncation
}
__device__ __forceinline__ double u2d(uint64_t v) {
    return __dmul_rn((double)v, 5.9604644775390625e-8);  // * 2^-24, exact
}
// T (+) T soft_add32 on masks: H/P/value out (alias-safe)
__device__ __forceinline__ void tadd(uint32_t Hx, uint32_t Px, uint64_t vx,
                                     uint32_t Hy, uint32_t Py, uint64_t vy,
                                     uint32_t& Ho, uint32_t& Po, uint64_t& vo) {
    uint32_t ho = hard_uu(vx, vy);
    uint32_t po = ho & (Hx & Hy & (Px | Py));
    uint64_t vv = tvalm(ho, po);
    Ho = ho; Po = po; vo = vv;
}

// ---- one MD5 compress over bit-sliced T-state -------------------------------
template<int BLK2>
__device__ void compress_fn(
    uint32_t& Ha, uint32_t& Pa, uint64_t& va,
    uint32_t& Hb, uint32_t& Pb, uint64_t& vb,
    uint32_t& Hc, uint32_t& Pc, uint64_t& vc,
    uint32_t& Hd, uint32_t& Pd, uint64_t& vd,
    const float (*sF)[64], const uint64_t (*sPM)[4],
    const double* wv, const uint32_t* m0, const uint32_t* m1, const uint32_t* m2)
{
    for (int ph = 0; ph < 4; ph++) {
        const float* ft = sF[ph];
        uint64_t pm0v = sPM[ph][0], pm1v = sPM[ph][1], pm3v = sPM[ph][3];
        uint32_t spk = (ph==0)?0x16110C07u:(ph==1)?0x140E0905u:(ph==2)?0x17100B04u:0x150F0A06u;
        int gmu = (ph==0)?1:(ph==1)?5:(ph==2)?3:7;
        int gad = (ph==0)?0:(ph==1)?1:(ph==2)?5:0;

        for (int r = 0; r < 16; r++) {
            // per-bit f values: sequential f64 chain + add1 deficit predicate
            double s = 0.0;
            uint32_t pred1 = 0;
#pragma unroll
            for (int j = 0; j < 32; j++) {
                uint32_t idx = ((Hb>>j)&1u) | (((Pb>>j)&1u)<<1)
                             | (((Hc>>j)&1u)<<2) | (((Pc>>j)&1u)<<3)
                             | (((Hd>>j)&1u)<<4) | (((Pd>>j)&1u)<<5);
                uint32_t fb = __float_as_uint(ft[idx]);
                uint32_t tb = ((fb<<1)==0u) ? 0u : (fb + ((uint32_t)j<<23)); // f*2^j exact
                s = __dadd_rn(s, (double)__uint_as_float(tb));
                uint32_t ast = ((Ha>>j)&1u) | (((Pa>>j)&1u)<<1);
                uint64_t pmv = (ast==0u)?pm0v:((ast==3u)?pm3v:pm1v);
                pred1 |= (((uint32_t)(pmv>>idx))&1u) << j;
            }
            // add1: f + a  (fine x T)
            double sv = __dadd_rn(s, u2d(va));
            uint32_t H1 = (uint32_t)(uint64_t)sv;     // floor(fmod(.,2^32))
            uint32_t P1 = H1 & pred1;
            uint64_t v1 = tvalm(H1, P1);
            // add2: + K[i]  (T x hard)
            int i = ph*16 + r;
            uint32_t Km = cK[i];
            uint32_t H2, P2; uint64_t v2;
            tadd(H1, P1, v1, Km, 0u, ((uint64_t)Km)<<24, H2, P2, v2);
            // add3: + word[g]
            int g = (gmu * r + gad) & 15;
            uint32_t H3, P3;
            if (BLK2) {
                uint32_t pw = (g==0) ? 0x80u : ((g==14) ? 0x200u : 0u);
                H3 = hard_uu(v2, ((uint64_t)pw)<<24);
                P3 = H3 & (P2 & pw);
            } else {
                double s3 = __dadd_rn(u2d(v2), wv[g]);
                H3 = (uint32_t)(uint64_t)s3;
                uint32_t pr = (~H2 & m0[g]) | ((H2 & ~P2) & m1[g]) | (P2 & m2[g]);
                P3 = H3 & pr;
            }
            // left-rotate by S[i], then b = soft_add32(b, rot)
            int sh = (spk >> (8*(r & 3))) & 31;
            uint32_t H3r = __funnelshift_l(H3, H3, sh);
            uint32_t P3r = __funnelshift_l(P3, P3, sh);
            uint64_t v3 = tvalm(H3r, P3r);
            uint32_t H4 = hard_uu(vb, v3);
            uint32_t P4 = H4 & (Hb & H3r & (Pb | P3r));
            uint64_t v4 = tvalm(H4, P4);
            // a,d,c = d,c,b ; b = new
            Ha=Hd; Pa=Pd; va=vd;
            Hd=Hc; Pd=Pc; vd=vc;
            Hc=Hb; Pc=Pb; vc=vb;
            Hb=H4; Pb=P4; vb=v4;
        }
    }
}

__global__ void __launch_bounds__(TPB)
softmd5_kernel(const float* __restrict__ in, float* __restrict__ out, int B)
{
    __shared__ float    sF[4][64];
    __shared__ uint64_t sPM[4][4];

    int t = threadIdx.x;
    for (int k = t; k < 256; k += TPB) {
        int ph = k >> 6, idx = k & 63;
        sF[ph][idx] = fphase(ph, decst(idx & 3), decst((idx>>2) & 3), decst((idx>>4) & 3));
    }
    __syncthreads();
    for (int k = t; k < 16; k += TPB) {
        int ph = k >> 2, st = k & 3;
        float av = decst(st);
        uint64_t m = 0;
        for (int idx = 0; idx < 64; idx++)
            m |= ((uint64_t)pbit(sF[ph][idx], av)) << idx;
        sPM[ph][st] = m;
    }
    __syncthreads();

    int row = blockIdx.x * TPB + t;
    if (row >= B) return;

    const float4* rp = reinterpret_cast<const float4*>(in + (size_t)row * 512);
    const float ONEME = __uint_as_float(0x3F7FFFFFu);

    // word values (sequential f64 chain) + add3 deficit masks per x-state
    double   wv[16];
    uint32_t m0[16], m1[16], m2[16];
#pragma unroll 1
    for (int g = 0; g < 16; g++) {
        double s = 0.0;
        uint32_t a0 = 0, a1 = 0, a2 = 0;
        for (int q = 0; q < 8; q++) {
            float4 w4 = rp[g*8 + q];
            float w[4] = { w4.x, w4.y, w4.z, w4.w };
#pragma unroll
            for (int u = 0; u < 4; u++) {
                int j = q*4 + u;
                uint32_t fb = __float_as_uint(w[u]);
                uint32_t tb = ((fb<<1)==0u) ? 0u : (fb + ((uint32_t)j<<23));
                s = __dadd_rn(s, (double)__uint_as_float(tb));
                a0 |= pbit(0.0f,  w[u]) << j;
                a1 |= pbit(1.0f,  w[u]) << j;
                a2 |= pbit(ONEME, w[u]) << j;
            }
        }
        wv[g] = s; m0[g] = a0; m1[g] = a1; m2[g] = a2;
    }

    // H-state (T-masks + cached value)
    uint32_t HA = 0x67452301u, PA = 0, HB = 0xefcdab89u, PB = 0;
    uint32_t HC = 0x98badcfeu, PC = 0, HD = 0x10325476u, PD = 0;
    uint64_t VA = ((uint64_t)HA)<<24, VB = ((uint64_t)HB)<<24;
    uint64_t VC = ((uint64_t)HC)<<24, VD = ((uint64_t)HD)<<24;

    // ---- block 1 ----
    {
        uint32_t ha=HA,pa=PA,hb=HB,pb=PB,hc=HC,pc=PC,hd=HD,pd=PD;
        uint64_t va=VA,vb=VB,vc=VC,vd=VD;
        compress_fn<0>(ha,pa,va, hb,pb,vb, hc,pc,vc, hd,pd,vd,
                       sF, sPM, wv, m0, m1, m2);
        tadd(HA,PA,VA, ha,pa,va, HA,PA,VA);
        tadd(HB,PB,VB, hb,pb,vb, HB,PB,VB);
        tadd(HC,PC,VC, hc,pc,vc, HC,PC,VC);
        tadd(HD,PD,VD, hd,pd,vd, HD,PD,VD);
    }
    // ---- block 2 (constant padding) ----
    {
        uint32_t ha=HA,pa=PA,hb=HB,pb=PB,hc=HC,pc=PC,hd=HD,pd=PD;
        uint64_t va=VA,vb=VB,vc=VC,vd=VD;
        compress_fn<1>(ha,pa,va, hb,pb,vb, hc,pc,vc, hd,pd,vd,
                       sF, sPM, wv, m0, m1, m2);
        tadd(HA,PA,VA, ha,pa,va, HA,PA,VA);
        tadd(HB,PB,VB, hb,pb,vb, HB,PB,VB);
        tadd(HC,PC,VC, hc,pc,vc, HC,PC,VC);
        tadd(HD,PD,VD, hd,pd,vd, HD,PD,VD);
    }

    // ---- emit 128 float bits -------------------------------------------------
    float4* op = reinterpret_cast<float4*>(out + (size_t)row * 128);
    uint32_t Hs[4] = { HA, HB, HC, HD }, Ps[4] = { PA, PB, PC, PD };
#pragma unroll
    for (int w = 0; w < 4; w++) {
        uint32_t Hm = Hs[w], Pm = Ps[w];
#pragma unroll
        for (int j = 0; j < 32; j += 4) {
            float4 f4;
            f4.x = __uint_as_float(((Hm>>(j+0))&1u) ? (((Pm>>(j+0))&1u)?0x3F7FFFFFu:0x3F800000u) : 0u);
            f4.y = __uint_as_float(((Hm>>(j+1))&1u) ? (((Pm>>(j+1))&1u)?0x3F7FFFFFu:0x3F800000u) : 0u);
            f4.z = __uint_as_float(((Hm>>(j+2))&1u) ? (((Pm>>(j+2))&1u)?0x3F7FFFFFu:0x3F800000u) : 0u);
            f4.w = __uint_as_float(((Hm>>(j+3))&1u) ? (((Pm>>(j+3))&1u)?0x3F7FFFFFu:0x3F800000u) : 0u);
            op[w*8 + (j>>2)] = f4;
        }
    }
}

extern "C" void kernel_launch(void* const* d_in, const int* in_sizes, int n_in,
                              void* d_out, int out_size)
{
    const float* in = (const float*)d_in[0];
    float* out = (float*)d_out;
    int B = in_sizes[0] / 512;            // 131072 rows
    int blocks = (B + TPB - 1) / TPB;
    softmd5_kernel<<<blocks, TPB>>>(in, out, B);
}

// round 6
// speedup vs baseline: 17.0032x; 1.0047x over previous
#include <cuda_runtime.h>
#include <stdint.h>

#define TPB 128

__constant__ uint32_t cK[64] = {
    0xd76aa478u,0xe8c7b756u,0x242070dbu,0xc1bdceeeu,
    0xf57c0fafu,0x4787c62au,0xa8304613u,0xfd469501u,
    0x698098d8u,0x8b44f7afu,0xffff5bb1u,0x895cd7beu,
    0x6b901122u,0xfd987193u,0xa679438eu,0x49b40821u,
    0xf61e2562u,0xc040b340u,0x265e5a51u,0xe9b6c7aau,
    0xd62f105du,0x02441453u,0xd8a1e681u,0xe7d3fbc8u,
    0x21e1cde6u,0xc33707d6u,0xf4d50d87u,0x455a14edu,
    0xa9e3e905u,0xfcefa3f8u,0x676f02d9u,0x8d2a4c8au,
    0xfffa3942u,0x8771f681u,0x6d9d6122u,0xfde5380cu,
    0xa4beea44u,0x4bdecfa9u,0xf6bb4b60u,0xbebfbc70u,
    0x289b7ec6u,0xeaa127fau,0xd4ef3085u,0x04881d05u,
    0xd9d4d039u,0xe6db99e5u,0x1fa27cf8u,0xc4ac5665u,
    0xf4292244u,0x432aff97u,0xab9423a7u,0xfc93a039u,
    0x655b59c3u,0x8f0ccc92u,0xffeff47du,0x85845dd1u,
    0x6fa87e4fu,0xfe2ce6e0u,0xa3014314u,0x4e0811a1u,
    0xf7537e82u,0xbd3af235u,0x2ad7d2bbu,0xeb86d391u };

// ---- f32 soft ops, exact IEEE-RN, reference association --------------------
__device__ __forceinline__ float fxor(float a, float b) {
    return __fsub_rn(__fadd_rn(a, b), __fmul_rn(__fmul_rn(2.0f, a), b));
}
__device__ __forceinline__ float fand(float a, float b) { return __fmul_rn(a, b); }
__device__ __forceinline__ float forr(float a, float b) {
    return __fsub_rn(__fadd_rn(a, b), __fmul_rn(a, b));
}
__device__ __forceinline__ float fnot(float a) { return __fsub_rn(1.0f, a); }

// state code: bit0 = hard bit, bit1 = deficit (value 1-2^-24)
__device__ __forceinline__ float decst(int st) {
    if (!(st & 1)) return 0.0f;
    return (st & 2) ? __uint_as_float(0x3F7FFFFFu) : 1.0f;
}
__device__ __forceinline__ float fphase(int ph, float b, float c, float d) {
    if (ph == 0) return forr(fand(b, c), fand(fnot(b), d));
    if (ph == 1) return forr(fand(d, b), fand(fnot(d), c));
    if (ph == 2) return fxor(fxor(b, c), d);
    return fxor(c, forr(b, fnot(d)));
}
// deficit predicate: soft_add32 result bit is (1-2^-24) iff hard=1 AND this
__device__ __forceinline__ uint32_t pbit(float x, float y) {
    float px = __fmul_rn(fxor(x, y), 0.5f);
    float r  = __fsub_rn(__fadd_rn(1.0f, px), px);
    return (__float_as_uint(r) != 0x3F800000u) ? 1u : 0u;
}

// ---- RN to 53-bit significand (ties-to-even) of a nonneg u64 ---------------
__device__ __forceinline__ uint64_t rn53(uint64_t x) {
    if (x < (1ull << 53)) return x;
    int n = 64 - __clzll(x);
    int s = n - 53;
    uint64_t keep = x >> s;
    uint64_t half = 1ull << (s - 1);
    uint64_t rem  = x & ((half << 1) - 1ull);
    keep += (rem > half) || (rem == half && (keep & 1ull));
    return keep << s;
}
// sequential f64 value of a T-valued word, 2^-24 units (R3-validated)
__device__ __forceinline__ uint64_t tvalm(uint32_t H, uint32_t P) {
    uint64_t E = (((uint64_t)(H & 0x1FFFFFFFu)) << 24) - (uint64_t)(P & 0x1FFFFFFFu);
#pragma unroll
    for (int i = 29; i < 32; i++) {
        uint64_t t = (((uint64_t)((H >> i) & 1u)) << (24 + i)) -
                     (((uint64_t)((P >> i) & 1u)) << i);
        E = rn53(E + t);
    }
    return E;
}
// hard bits of f64 add of two T-word values (both rn53-clean, 2^-24 units)
__device__ __forceinline__ uint32_t hard_uu(uint64_t a, uint64_t b) {
    uint64_t t = rn53(a + b);
    return (uint32_t)(t >> 24);   // floor + mod 2^32 via truncation
}
__device__ __forceinline__ double u2d(uint64_t v) {
    return __dmul_rn((double)v, 5.9604644775390625e-8);  // * 2^-24, exact
}
// T (+) T soft_add32 on masks: H/P/value out (alias-safe)
__device__ __forceinline__ void tadd(uint32_t Hx, uint32_t Px, uint64_t vx,
                                     uint32_t Hy, uint32_t Py, uint64_t vy,
                                     uint32_t& Ho, uint32_t& Po, uint64_t& vo) {
    uint32_t ho = hard_uu(vx, vy);
    uint32_t po = ho & (Hx & Hy & (Px | Py));
    uint64_t vv = tvalm(ho, po);
    Ho = ho; Po = po; vo = vv;
}

// ---- one MD5 compress over bit-sliced T-state -------------------------------
template<int BLK2>
__device__ void compress_fn(
    uint32_t& Ha, uint32_t& Pa, uint64_t& va,
    uint32_t& Hb, uint32_t& Pb, uint64_t& vb,
    uint32_t& Hc, uint32_t& Pc, uint64_t& vc,
    uint32_t& Hd, uint32_t& Pd, uint64_t& vd,
    const float (*sF)[64], const uint64_t (*sPM)[4],
    const double* wv, const uint32_t* m0, const uint32_t* m1, const uint32_t* m2)
{
    for (int ph = 0; ph < 4; ph++) {
        const float* ft = sF[ph];
        uint64_t pm0v = sPM[ph][0], pm1v = sPM[ph][1], pm3v = sPM[ph][3];
        uint32_t spk = (ph==0)?0x16110C07u:(ph==1)?0x140E0905u:(ph==2)?0x17100B04u:0x150F0A06u;
        int gmu = (ph==0)?1:(ph==1)?5:(ph==2)?3:7;
        int gad = (ph==0)?0:(ph==1)?1:(ph==2)?5:0;

        for (int r = 0; r < 16; r++) {
            // per-bit f values: sequential f64 chain + add1 deficit predicate
            double s = 0.0;
            uint32_t pred1 = 0;
#pragma unroll
            for (int j = 0; j < 32; j++) {
                uint32_t idx = ((Hb>>j)&1u) | (((Pb>>j)&1u)<<1)
                             | (((Hc>>j)&1u)<<2) | (((Pc>>j)&1u)<<3)
                             | (((Hd>>j)&1u)<<4) | (((Pd>>j)&1u)<<5);
                uint32_t fb = __float_as_uint(ft[idx]);
                uint32_t tb = ((fb<<1)==0u) ? 0u : (fb + ((uint32_t)j<<23)); // f*2^j exact
                s = __dadd_rn(s, (double)__uint_as_float(tb));
                uint32_t ast = ((Ha>>j)&1u) | (((Pa>>j)&1u)<<1);
                uint64_t pmv = (ast==0u)?pm0v:((ast==3u)?pm3v:pm1v);
                pred1 |= (((uint32_t)(pmv>>idx))&1u) << j;
            }
            // add1: f + a  (fine x T)
            double sv = __dadd_rn(s, u2d(va));
            uint32_t H1 = (uint32_t)(uint64_t)sv;     // floor(fmod(.,2^32))
            uint32_t P1 = H1 & pred1;
            uint64_t v1 = tvalm(H1, P1);
            // add2: + K[i]  (T x hard)
            int i = ph*16 + r;
            uint32_t Km = cK[i];
            uint32_t H2, P2; uint64_t v2;
            tadd(H1, P1, v1, Km, 0u, ((uint64_t)Km)<<24, H2, P2, v2);
            // add3: + word[g]
            int g = (gmu * r + gad) & 15;
            uint32_t H3, P3;
            if (BLK2) {
                uint32_t pw = (g==0) ? 0x80u : ((g==14) ? 0x200u : 0u);
                H3 = hard_uu(v2, ((uint64_t)pw)<<24);
                P3 = H3 & (P2 & pw);
            } else {
                double s3 = __dadd_rn(u2d(v2), wv[g]);
                H3 = (uint32_t)(uint64_t)s3;
                uint32_t pr = (~H2 & m0[g]) | ((H2 & ~P2) & m1[g]) | (P2 & m2[g]);
                P3 = H3 & pr;
            }
            // left-rotate by S[i], then b = soft_add32(b, rot)
            int sh = (spk >> (8*(r & 3))) & 31;
            uint32_t H3r = __funnelshift_l(H3, H3, sh);
            uint32_t P3r = __funnelshift_l(P3, P3, sh);
            uint64_t v3 = tvalm(H3r, P3r);
            uint32_t H4 = hard_uu(vb, v3);
            uint32_t P4 = H4 & (Hb & H3r & (Pb | P3r));
            uint64_t v4 = tvalm(H4, P4);
            // a,d,c = d,c,b ; b = new
            Ha=Hd; Pa=Pd; va=vd;
            Hd=Hc; Pd=Pc; vd=vc;
            Hc=Hb; Pc=Pb; vc=vb;
            Hb=H4; Pb=P4; vb=v4;
        }
    }
}

__global__ void __launch_bounds__(TPB)
softmd5_kernel(const float* __restrict__ in, float* __restrict__ out, int B)
{
    __shared__ float    sF[4][64];
    __shared__ uint64_t sPM[4][4];

    int t = threadIdx.x;
    for (int k = t; k < 256; k += TPB) {
        int ph = k >> 6, idx = k & 63;
        sF[ph][idx] = fphase(ph, decst(idx & 3), decst((idx>>2) & 3), decst((idx>>4) & 3));
    }
    __syncthreads();
    for (int k = t; k < 16; k += TPB) {
        int ph = k >> 2, st = k & 3;
        float av = decst(st);
        uint64_t m = 0;
        for (int idx = 0; idx < 64; idx++)
            m |= ((uint64_t)pbit(sF[ph][idx], av)) << idx;
        sPM[ph][st] = m;
    }
    __syncthreads();

    int row = blockIdx.x * TPB + t;
    if (row >= B) return;

    const float4* rp = reinterpret_cast<const float4*>(in + (size_t)row * 512);
    const float ONEME = __uint_as_float(0x3F7FFFFFu);

    // word values (sequential f64 chain) + add3 deficit masks per x-state
    double   wv[16];
    uint32_t m0[16], m1[16], m2[16];
#pragma unroll 1
    for (int g = 0; g < 16; g++) {
        double s = 0.0;
        uint32_t a0 = 0, a1 = 0, a2 = 0;
        for (int q = 0; q < 8; q++) {
            float4 w4 = rp[g*8 + q];
            float w[4] = { w4.x, w4.y, w4.z, w4.w };
#pragma unroll
            for (int u = 0; u < 4; u++) {
                int j = q*4 + u;
                uint32_t fb = __float_as_uint(w[u]);
                uint32_t tb = ((fb<<1)==0u) ? 0u : (fb + ((uint32_t)j<<23));
                s = __dadd_rn(s, (double)__uint_as_float(tb));
                a0 |= pbit(0.0f,  w[u]) << j;
                a1 |= pbit(1.0f,  w[u]) << j;
                a2 |= pbit(ONEME, w[u]) << j;
            }
        }
        wv[g] = s; m0[g] = a0; m1[g] = a1; m2[g] = a2;
    }

    // H-state (T-masks + cached value)
    uint32_t HA = 0x67452301u, PA = 0, HB = 0xefcdab89u, PB = 0;
    uint32_t HC = 0x98badcfeu, PC = 0, HD = 0x10325476u, PD = 0;
    uint64_t VA = ((uint64_t)HA)<<24, VB = ((uint64_t)HB)<<24;
    uint64_t VC = ((uint64_t)HC)<<24, VD = ((uint64_t)HD)<<24;

    // ---- block 1 ----
    {
        uint32_t ha=HA,pa=PA,hb=HB,pb=PB,hc=HC,pc=PC,hd=HD,pd=PD;
        uint64_t va=VA,vb=VB,vc=VC,vd=VD;
        compress_fn<0>(ha,pa,va, hb,pb,vb, hc,pc,vc, hd,pd,vd,
                       sF, sPM, wv, m0, m1, m2);
        tadd(HA,PA,VA, ha,pa,va, HA,PA,VA);
        tadd(HB,PB,VB, hb,pb,vb, HB,PB,VB);
        tadd(HC,PC,VC, hc,pc,vc, HC,PC,VC);
        tadd(HD,PD,VD, hd,pd,vd, HD,PD,VD);
    }
    // ---- block 2 (constant padding) ----
    {
        uint32_t ha=HA,pa=PA,hb=HB,pb=PB,hc=HC,pc=PC,hd=HD,pd=PD;
        uint64_t va=VA,vb=VB,vc=VC,vd=VD;
        compress_fn<1>(ha,pa,va, hb,pb,vb, hc,pc,vc, hd,pd,vd,
                       sF, sPM, wv, m0, m1, m2);
        tadd(HA,PA,VA, ha,pa,va, HA,PA,VA);
        tadd(HB,PB,VB, hb,pb,vb, HB,PB,VB);
        tadd(HC,PC,VC, hc,pc,vc, HC,PC,VC);
        tadd(HD,PD,VD, hd,pd,vd, HD,PD,VD);
    }

    // ---- emit 128 float bits -------------------------------------------------
    float4* op = reinterpret_cast<float4*>(out + (size_t)row * 128);
    uint32_t Hs[4] = { HA, HB, HC, HD }, Ps[4] = { PA, PB, PC, PD };
#pragma unroll
    for (int w = 0; w < 4; w++) {
        uint32_t Hm = Hs[w], Pm = Ps[w];
#pragma unroll
        for (int j = 0; j < 32; j += 4) {
            float4 f4;
            f4.x = __uint_as_float(((Hm>>(j+0))&1u) ? (((Pm>>(j+0))&1u)?0x3F7FFFFFu:0x3F800000u) : 0u);
            f4.y = __uint_as_float(((Hm>>(j+1))&1u) ? (((Pm>>(j+1))&1u)?0x3F7FFFFFu:0x3F800000u) : 0u);
            f4.z = __uint_as_float(((Hm>>(j+2))&1u) ? (((Pm>>(j+2))&1u)?0x3F7FFFFFu:0x3F800000u) : 0u);
            f4.w = __uint_as_float(((Hm>>(j+3))&1u) ? (((Pm>>(j+3))&1u)?0x3F7FFFFFu:0x3F800000u) : 0u);
            op[w*8 + (j>>2)] = f4;
        }
    }
}

extern "C" void kernel_launch(void* const* d_in, const int* in_sizes, int n_in,
                              void* d_out, int out_size)
{
    const float* in = (const float*)d_in[0];
    float* out = (float*)d_out;
    int B = in_sizes[0] / 512;            // 131072 rows
    int blocks = (B + TPB - 1) / TPB;
    softmd5_kernel<<<blocks, TPB>>>(in, out, B);
}

// round 7
// speedup vs baseline: 25.0486x; 1.4732x over previous
#include <cuda_runtime.h>
#include <stdint.h>

#define TPB 128

__constant__ uint32_t cK[64] = {
    0xd76aa478u,0xe8c7b756u,0x242070dbu,0xc1bdceeeu,
    0xf57c0fafu,0x4787c62au,0xa8304613u,0xfd469501u,
    0x698098d8u,0x8b44f7afu,0xffff5bb1u,0x895cd7beu,
    0x6b901122u,0xfd987193u,0xa679438eu,0x49b40821u,
    0xf61e2562u,0xc040b340u,0x265e5a51u,0xe9b6c7aau,
    0xd62f105du,0x02441453u,0xd8a1e681u,0xe7d3fbc8u,
    0x21e1cde6u,0xc33707d6u,0xf4d50d87u,0x455a14edu,
    0xa9e3e905u,0xfcefa3f8u,0x676f02d9u,0x8d2a4c8au,
    0xfffa3942u,0x8771f681u,0x6d9d6122u,0xfde5380cu,
    0xa4beea44u,0x4bdecfa9u,0xf6bb4b60u,0xbebfbc70u,
    0x289b7ec6u,0xeaa127fau,0xd4ef3085u,0x04881d05u,
    0xd9d4d039u,0xe6db99e5u,0x1fa27cf8u,0xc4ac5665u,
    0xf4292244u,0x432aff97u,0xab9423a7u,0xfc93a039u,
    0x655b59c3u,0x8f0ccc92u,0xffeff47du,0x85845dd1u,
    0x6fa87e4fu,0xfe2ce6e0u,0xa3014314u,0x4e0811a1u,
    0xf7537e82u,0xbd3af235u,0x2ad7d2bbu,0xeb86d391u };

__constant__ uint8_t cS[64] = {
    7,12,17,22, 7,12,17,22, 7,12,17,22, 7,12,17,22,
    5, 9,14,20, 5, 9,14,20, 5, 9,14,20, 5, 9,14,20,
    4,11,16,23, 4,11,16,23, 4,11,16,23, 4,11,16,23,
    6,10,15,21, 6,10,15,21, 6,10,15,21, 6,10,15,21 };

__constant__ uint8_t cG[64] = {
    0,1,2,3,4,5,6,7,8,9,10,11,12,13,14,15,
    1,6,11,0,5,10,15,4,9,14,3,8,13,2,7,12,
    5,8,11,14,1,4,7,10,13,0,3,6,9,12,15,2,
    0,7,14,5,12,3,10,1,8,15,6,13,4,11,2,9 };

// ---- f32 soft ops, exact IEEE-RN, reference association --------------------
__device__ __forceinline__ float fxor(float a, float b) {
    return __fsub_rn(__fadd_rn(a, b), __fmul_rn(__fmul_rn(2.0f, a), b));
}
__device__ __forceinline__ float fand(float a, float b) { return __fmul_rn(a, b); }
__device__ __forceinline__ float forr(float a, float b) {
    return __fsub_rn(__fadd_rn(a, b), __fmul_rn(a, b));
}
__device__ __forceinline__ float fnot(float a) { return __fsub_rn(1.0f, a); }

// state code: bit0 = hard bit, bit1 = deficit (value 1-2^-24)
__device__ __forceinline__ float decst(int st) {
    if (!(st & 1)) return 0.0f;
    return (st & 2) ? __uint_as_float(0x3F7FFFFFu) : 1.0f;
}
__device__ __forceinline__ float fphase(int ph, float b, float c, float d) {
    if (ph == 0) return forr(fand(b, c), fand(fnot(b), d));
    if (ph == 1) return forr(fand(d, b), fand(fnot(d), c));
    if (ph == 2) return fxor(fxor(b, c), d);
    return fxor(c, forr(b, fnot(d)));
}
// deficit predicate: soft_add32 result bit is (1-2^-24) iff hard=1 AND this
// (x = first operand of soft_xor: proxy uses fl(2x)*y)
__device__ __forceinline__ uint32_t pbit(float x, float y) {
    float px = __fmul_rn(fxor(x, y), 0.5f);
    float r  = __fsub_rn(__fadd_rn(1.0f, px), px);
    return (__float_as_uint(r) != 0x3F800000u) ? 1u : 0u;
}

// ---- RN to 53-bit significand (ties-to-even) of a nonneg u64 ---------------
__device__ __forceinline__ uint64_t rn53(uint64_t x) {
    if (x < (1ull << 53)) return x;
    int n = 64 - __clzll(x);
    int s = n - 53;
    uint64_t keep = x >> s;
    uint64_t half = 1ull << (s - 1);
    uint64_t rem  = x & ((half << 1) - 1ull);
    keep += (rem > half) || (rem == half && (keep & 1ull));
    return keep << s;
}
// sequential f64 value of a T-valued word, 2^-24 units (R3-validated)
__device__ __forceinline__ uint64_t tvalm(uint32_t H, uint32_t P) {
    uint64_t E = (((uint64_t)(H & 0x1FFFFFFFu)) << 24) - (uint64_t)(P & 0x1FFFFFFFu);
#pragma unroll
    for (int i = 29; i < 32; i++) {
        uint64_t t = (((uint64_t)((H >> i) & 1u)) << (24 + i)) -
                     (((uint64_t)((P >> i) & 1u)) << i);
        E = rn53(E + t);
    }
    return E;
}
// hard bits of f64 add of two T-word values (rn53-clean, 2^-24 units);
// truncating u32 cast == floor(fmod(., 2^32)) since at most one wrap.
__device__ __forceinline__ uint32_t hard_uu(uint64_t a, uint64_t b) {
    return (uint32_t)(rn53(a + b) >> 24);
}
__device__ __forceinline__ double u2d(uint64_t v) {
    return __dmul_rn((double)v, 5.9604644775390625e-8);  // * 2^-24, exact
}
// T (+) T soft_add32 on masks (alias-safe)
__device__ __forceinline__ void tadd(uint32_t Hx, uint32_t Px, uint64_t vx,
                                     uint32_t Hy, uint32_t Py, uint64_t vy,
                                     uint32_t& Ho, uint32_t& Po, uint64_t& vo) {
    uint32_t ho = hard_uu(vx, vy);
    uint32_t po = ho & (Hx & Hy & (Px | Py));
    uint64_t vv = tvalm(ho, po);
    Ho = ho; Po = po; vo = vv;
}

// ---- one MD5 compress over bit-sliced T-state -------------------------------
template<int BLK2>
__device__ void compress_fn(
    uint32_t& Ha, uint32_t& Pa, uint64_t& va,
    uint32_t& Hb, uint32_t& Pb, uint64_t& vb,
    uint32_t& Hc, uint32_t& Pc, uint64_t& vc,
    uint32_t& Hd, uint32_t& Pd, uint64_t& vd,
    const ulonglong2 (*sT)[64],
    const double* wv, const uint32_t* m0, const uint32_t* x1, const uint32_t* x2)
{
#pragma unroll 1
    for (int i = 0; i < 64; i++) {
        const ulonglong2* ft = sT[i >> 4];
        double s = 0.0;
        uint32_t pred1 = 0;
#pragma unroll
        for (int j = 0; j < 32; j++) {
            uint32_t idx = ((Hb >> j) & 1u) | (((Pb >> j) & 1u) << 1)
                         | (((Hc >> j) & 1u) << 2) | (((Pc >> j) & 1u) << 3)
                         | (((Hd >> j) & 1u) << 4) | (((Pd >> j) & 1u) << 5);
            ulonglong2 e = ft[idx];
            // fma(f, 2^j, s) == fl(s + exact(f*2^j)): identical to reference chain
            s = __fma_rn(__longlong_as_double((long long)e.x), (double)(1u << j), s);
            uint32_t ast = ((Ha >> j) & 1u) | (((Pa >> j) & 1u) << 1);
            pred1 |= (((uint32_t)e.y >> ast) & 1u) << j;
        }
        // add1: f + a   (fine x T)
        double sv = __dadd_rn(s, u2d(va));
        uint32_t H1 = (uint32_t)(uint64_t)sv;          // floor(fmod(., 2^32))
        uint32_t P1 = H1 & pred1;
        uint64_t v1 = tvalm(H1, P1);
        // add2: + K[i]  (T x hard)
        uint32_t Km = cK[i];
        uint32_t H2 = hard_uu(v1, ((uint64_t)Km) << 24);
        uint32_t P2 = H2 & (Km & P1);
        uint64_t v2 = tvalm(H2, P2);
        // add3: + word[g]
        int g = cG[i];
        uint32_t H3, P3;
        if (BLK2) {
            uint32_t pw = (g == 0) ? 0x80u : ((g == 14) ? 0x200u : 0u);
            H3 = hard_uu(v2, ((uint64_t)pw) << 24);
            P3 = H3 & (P2 & pw);
        } else {
            double s3 = __dadd_rn(u2d(v2), wv[g]);
            H3 = (uint32_t)(uint64_t)s3;
            uint32_t pr = m0[g] ^ (H2 & x1[g]) ^ (P2 & x2[g]);
            P3 = H3 & pr;
        }
        // rotate, then b = soft_add32(b, rot)
        int sh = cS[i];
        uint32_t H3r = __funnelshift_l(H3, H3, sh);
        uint32_t P3r = __funnelshift_l(P3, P3, sh);
        uint64_t v3 = tvalm(H3r, P3r);
        uint32_t H4 = hard_uu(vb, v3);
        uint32_t P4 = H4 & (Hb & H3r & (Pb | P3r));
        uint64_t v4 = tvalm(H4, P4);
        Ha = Hd; Pa = Pd; va = vd;
        Hd = Hc; Pd = Pc; vd = vc;
        Hc = Hb; Pc = Pb; vc = vb;
        Hb = H4; Pb = P4; vb = v4;
    }
}

__global__ void __launch_bounds__(TPB)
softmd5_kernel(const float* __restrict__ in, float* __restrict__ out, int B)
{
    __shared__ ulonglong2 sT[4][64];     // {f as f64 bits, pred-pack (bits 0,1,3)}

    int t = threadIdx.x;
    const float ONEME = __uint_as_float(0x3F7FFFFFu);
    for (int k = t; k < 256; k += TPB) {
        int ph = k >> 6, idx = k & 63;
        float f = fphase(ph, decst(idx & 3), decst((idx >> 2) & 3), decst((idx >> 4) & 3));
        uint32_t pp = pbit(f, 0.0f) | (pbit(f, 1.0f) << 1) | (pbit(f, ONEME) << 3);
        sT[ph][idx] = make_ulonglong2(
            (unsigned long long)__double_as_longlong((double)f),
            (unsigned long long)pp);
    }
    __syncthreads();

    int row = blockIdx.x * TPB + t;
    if (row >= B) return;

    const float4* rp = reinterpret_cast<const float4*>(in + (size_t)row * 512);

    // word values (sequential f64 chain) + add3 deficit masks (xor-select form)
    double   wv[16];
    uint32_t m0[16], x1[16], x2[16];
#pragma unroll 1
    for (int g = 0; g < 16; g++) {
        double s = 0.0;
        uint32_t a0 = 0, a1 = 0, a2 = 0;
        for (int q = 0; q < 8; q++) {
            float4 w4 = rp[g * 8 + q];
            float w[4] = { w4.x, w4.y, w4.z, w4.w };
#pragma unroll
            for (int u = 0; u < 4; u++) {
                int j = q * 4 + u;
                s = __fma_rn((double)w[u], (double)(1u << j), s);  // exact product
                a0 |= pbit(0.0f,  w[u]) << j;
                a1 |= pbit(1.0f,  w[u]) << j;
                a2 |= pbit(ONEME, w[u]) << j;
            }
        }
        wv[g] = s; m0[g] = a0; x1[g] = a0 ^ a1; x2[g] = a1 ^ a2;
    }

    // H-state (T-masks + cached f64 value in 2^-24 units)
    uint32_t HA = 0x67452301u, PA = 0, HB = 0xefcdab89u, PB = 0;
    uint32_t HC = 0x98badcfeu, PC = 0, HD = 0x10325476u, PD = 0;
    uint64_t VA = ((uint64_t)HA) << 24, VB = ((uint64_t)HB) << 24;
    uint64_t VC = ((uint64_t)HC) << 24, VD = ((uint64_t)HD) << 24;

    // ---- block 1 ----
    {
        uint32_t ha=HA,pa=PA,hb=HB,pb=PB,hc=HC,pc=PC,hd=HD,pd=PD;
        uint64_t va=VA,vb=VB,vc=VC,vd=VD;
        compress_fn<0>(ha,pa,va, hb,pb,vb, hc,pc,vc, hd,pd,vd,
                       sT, wv, m0, x1, x2);
        tadd(HA,PA,VA, ha,pa,va, HA,PA,VA);
        tadd(HB,PB,VB, hb,pb,vb, HB,PB,VB);
        tadd(HC,PC,VC, hc,pc,vc, HC,PC,VC);
        tadd(HD,PD,VD, hd,pd,vd, HD,PD,VD);
    }
    // ---- block 2 (constant padding) ----
    {
        uint32_t ha=HA,pa=PA,hb=HB,pb=PB,hc=HC,pc=PC,hd=HD,pd=PD;
        uint64_t va=VA,vb=VB,vc=VC,vd=VD;
        compress_fn<1>(ha,pa,va, hb,pb,vb, hc,pc,vc, hd,pd,vd,
                       sT, wv, m0, x1, x2);
        tadd(HA,PA,VA, ha,pa,va, HA,PA,VA);
        tadd(HB,PB,VB, hb,pb,vb, HB,PB,VB);
        tadd(HC,PC,VC, hc,pc,vc, HC,PC,VC);
        tadd(HD,PD,VD, hd,pd,vd, HD,PD,VD);
    }

    // ---- emit 128 float bits ----
    float4* op = reinterpret_cast<float4*>(out + (size_t)row * 128);
    uint32_t Hs[4] = { HA, HB, HC, HD }, Ps[4] = { PA, PB, PC, PD };
#pragma unroll
    for (int w = 0; w < 4; w++) {
        uint32_t Hm = Hs[w], Pm = Ps[w];
#pragma unroll
        for (int j = 0; j < 32; j += 4) {
            float4 f4;
            f4.x = __uint_as_float(((Hm>>(j+0))&1u) ? (((Pm>>(j+0))&1u)?0x3F7FFFFFu:0x3F800000u) : 0u);
            f4.y = __uint_as_float(((Hm>>(j+1))&1u) ? (((Pm>>(j+1))&1u)?0x3F7FFFFFu:0x3F800000u) : 0u);
            f4.z = __uint_as_float(((Hm>>(j+2))&1u) ? (((Pm>>(j+2))&1u)?0x3F7FFFFFu:0x3F800000u) : 0u);
            f4.w = __uint_as_float(((Hm>>(j+3))&1u) ? (((Pm>>(j+3))&1u)?0x3F7FFFFFu:0x3F800000u) : 0u);
            op[w*8 + (j>>2)] = f4;
        }
    }
}

extern "C" void kernel_launch(void* const* d_in, const int* in_sizes, int n_in,
                              void* d_out, int out_size)
{
    const float* in = (const float*)d_in[0];
    float* out = (float*)d_out;
    int B = in_sizes[0] / 512;            // 131072 rows
    int blocks = (B + TPB - 1) / TPB;
    softmd5_kernel<<<blocks, TPB>>>(in, out, B);
}